// round 9
// baseline (speedup 1.0000x reference)
#include <cuda_runtime.h>
#include <cstdint>

// ---------------------------------------------------------------------------
// ContourRec: 2-level contourlet DFB reconstruction (4 subbands).
// Stage A (fbrec '2c','per'): fused per-image kernel, 1024 thr, NON-OVERLAPPING
//   single-chunk partition (8 groups x 128 lanes), P1=131 (bank-conflict-free).
// Stage B (fbrec '1r','qper_col') + qprec '1r': fused 2-CTA-cluster kernel
//   (unchanged from R8: 75.7us).
// ---------------------------------------------------------------------------

#define P1 131
#define INV_SQRT2 0.70710678118654752f
#define SQRT2     1.41421356237309505f

__device__ float g_x[16777216];     // 8*64*128*256 (stage-A output)

#define DEF_FILT const float FILT[12] = {0.0144f, 0.0272f, 0.0526f, 0.0972f, \
    0.193f, 0.63f, -0.63f, -0.193f, -0.0972f, -0.0526f, -0.0272f, -0.0144f}

// ---------------- Stage A: fused per-image kernel (1024 thr) ---------------
// smem: A (Y0 -> p0), B (scratch), C (t1 -> p1): 3*128*131*4 = 201,216 B.
// Partition: tid>>7 = group g in [0,8), each thread exactly ONE 16-row (hconv)
// or 16-col (wconv) chunk -> no duplicated work (R4's bug), no spill (~40 regs).

__device__ __forceinline__ void hconvA(const float* __restrict__ S,
                                       float* __restrict__ D, int off, int tid)
{
    DEF_FILT;
    const int j  = tid & 127;
    const int r0 = (tid >> 7) * 16;           // rows [r0, r0+16)
    const int ib = r0 - off;
    float buf[27];
    #pragma unroll
    for (int k = 0; k < 27; ++k) buf[k] = S[((ib + k) & 127) * P1 + j];
    #pragma unroll
    for (int r = 0; r < 16; ++r) {
        float acc = 0.f;
        #pragma unroll
        for (int t = 0; t < 12; ++t) acc = fmaf(FILT[t], buf[r + t], acc);
        D[(r0 + r) * P1 + j] = acc;
    }
}

template <bool COMBINE>
__device__ __forceinline__ void wconvA(const float* __restrict__ S,
                                       float* __restrict__ D, int off, int tid)
{
    DEF_FILT;
    const int i  = tid & 127;
    const int c0 = (tid >> 7) * 16;           // cols [c0, c0+16)
    const float* row = S + i * P1;
    const int jb = c0 - off;
    float buf[27];
    #pragma unroll
    for (int k = 0; k < 27; ++k) buf[k] = row[(jb + k) & 127];
    #pragma unroll
    for (int r = 0; r < 16; ++r) {
        float acc = 0.f;
        #pragma unroll
        for (int t = 0; t < 12; ++t) acc = fmaf(FILT[t], buf[r + t], acc);
        const int o = i * P1 + c0 + r;
        if (COMBINE) D[o] = SQRT2 * D[o] + acc;
        else         D[o] = acc;
    }
}

__global__ __launch_bounds__(1024) void stageA_kernel(
    const float* __restrict__ y0, const float* __restrict__ y1,
    const float* __restrict__ y2, const float* __restrict__ y3)
{
    extern __shared__ float sm[];
    float* A = sm;
    float* B = sm + 128 * P1;
    float* C = sm + 2 * 128 * P1;

    const int img = blockIdx.x;
    const int b = img >> 6, ch = img & 63;
    const float* gY0;
    const float* gY1;
    if (ch < 32) { gY0 = y1 + (b * 32 + ch) * 16384;
                   gY1 = y0 + (b * 32 + ch) * 16384; }
    else         { gY0 = y2 + (b * 32 + ch - 32) * 16384;
                   gY1 = y3 + (b * 32 + ch - 32) * 16384; }

    const int tid = threadIdx.x;

    for (int idx = tid; idx < 16384; idx += 1024)
        A[(idx >> 7) * P1 + (idx & 127)] = gY0[idx];
    __syncthreads();

    hconvA(A, B, 5, tid);
    __syncthreads();
    wconvA<false>(B, C, 5, tid);
    __syncthreads();

    for (int idx = tid; idx < 16384; idx += 1024) {
        const int o = (idx >> 7) * P1 + (idx & 127);
        C[o] = -INV_SQRT2 * (gY1[idx] + C[o]);
    }
    __syncthreads();

    hconvA(C, B, 6, tid);
    __syncthreads();
    wconvA<true>(B, A, 6, tid);
    __syncthreads();

    float* gx = g_x + img * 32768;
    for (int idx = tid; idx < 32768; idx += 1024) {
        const int i = idx >> 8, j = idx & 255;
        const int col = (i + j) & 255;
        const int h = col >> 1;
        float v;
        if (col & 1) v = C[((i - 1 - h) & 127) * P1 + h];
        else         v = A[((i - h) & 127) * P1 + h];
        gx[idx] = v;
    }
}

// ---------------- Fused Stage B + qprec (2-CTA cluster, 1024 thr) ----------
// (unchanged from R8)

#define QP  264                     // q pitch: bank-free phase-3 reads
#define EP  268                     // 16B-aligned rows
#define Q0OFF 0                     // Q0: 64 x 264
#define Q1OFF 16912                 // 64*264 + 16 -> Q1 banks complement Q0's
#define EOFF  33824                 // E: 75 x 268 (16B aligned)
#define SMB_FLOATS (33824 + 75 * 268)
#define SMB_BYTES (SMB_FLOATS * 4)  // 215,696 B

__device__ __forceinline__ uint32_t smem_u32(const void* p) {
    uint32_t a;
    asm("{ .reg .u64 t; cvta.to.shared.u64 t, %1; cvt.u32.u64 %0, t; }"
        : "=r"(a) : "l"(p));
    return a;
}
__device__ __forceinline__ uint32_t mapa_rank(uint32_t addr, uint32_t rank) {
    uint32_t r;
    asm("mapa.shared::cluster.u32 %0, %1, %2;" : "=r"(r) : "r"(addr), "r"(rank));
    return r;
}
__device__ __forceinline__ float ld_dsm(uint32_t addr) {
    float v;
    asm volatile("ld.shared::cluster.f32 %0, [%1];" : "=f"(v) : "r"(addr));
    return v;
}
#define CLUSTER_SYNC() do { \
    asm volatile("barrier.cluster.arrive.aligned;" ::: "memory"); \
    asm volatile("barrier.cluster.wait.aligned;"  ::: "memory"); } while (0)

// In-place row conv on E row k: out[c] = sum_u FILT[u]*Ein[c+u], c in [0,256).
__device__ __forceinline__ void rowconv_inplace(float* __restrict__ erow,
                                                int lane)
{
    DEF_FILT;
    const float* tr = erow + 8 * lane;
    float w[20];
    const float4 a0 = *(const float4*)(tr);
    const float4 a1 = *(const float4*)(tr + 4);
    const float4 a2 = *(const float4*)(tr + 8);
    const float4 a3 = *(const float4*)(tr + 12);
    const float4 a4 = *(const float4*)(tr + 16);
    w[0]=a0.x; w[1]=a0.y; w[2]=a0.z; w[3]=a0.w;
    w[4]=a1.x; w[5]=a1.y; w[6]=a1.z; w[7]=a1.w;
    w[8]=a2.x; w[9]=a2.y; w[10]=a2.z; w[11]=a2.w;
    w[12]=a3.x; w[13]=a3.y; w[14]=a3.z; w[15]=a3.w;
    w[16]=a4.x; w[17]=a4.y; w[18]=a4.z; w[19]=a4.w;
    float acc[8];
    #pragma unroll
    for (int m = 0; m < 8; ++m) acc[m] = 0.f;
    #pragma unroll
    for (int u = 0; u < 12; ++u) {
        const float fv = FILT[u];
        #pragma unroll
        for (int m = 0; m < 8; ++m)
            acc[m] = fmaf(fv, w[m + u], acc[m]);
    }
    __syncwarp();
    float4 o0, o1;
    o0.x=acc[0]; o0.y=acc[1]; o0.z=acc[2]; o0.w=acc[3];
    o1.x=acc[4]; o1.y=acc[5]; o1.z=acc[6]; o1.w=acc[7];
    *(float4*)(erow + 8 * lane)     = o0;
    *(float4*)(erow + 8 * lane + 4) = o1;
}

__device__ __forceinline__ float4 f4fma(float s, float4 v, float4 a) {
    a.x = fmaf(s, v.x, a.x); a.y = fmaf(s, v.y, a.y);
    a.z = fmaf(s, v.z, a.z); a.w = fmaf(s, v.w, a.w);
    return a;
}

__global__ __launch_bounds__(1024) __cluster_dims__(2, 1, 1)
void stageB_fused(float* __restrict__ out)
{
    extern __shared__ float smB[];
    float* Q0 = smB + Q0OFF;
    float* Q1 = smB + Q1OFF;
    float* E  = smB + EOFF;

    const int tid  = threadIdx.x;
    const int lane = tid & 31;
    const int wrp  = tid >> 5;                // 0..31
    uint32_t hr;
    asm("mov.u32 %0, %%cluster_ctarank;" : "=r"(hr));
    const int h    = (int)hr;
    const int img2 = blockIdx.x >> 1;
    const int x0base = ((img2 >> 5) * 64 + (img2 & 31)) * 32768;
    const float* x0g = g_x + x0base;
    const float* x1g = x0g + 32 * 32768;

    const uint32_t q1PeerBase = mapa_rank(smem_u32(Q1), hr ^ 1u);

    DEF_FILT;

    // ==== phase 1: Q1 = -1/sqrt2 (x1 + sefilter(x0, off=5)) ===============
    {
        const int rowbase = 64 * h - 5;
        for (int k = wrp; k < 75; k += 32) {
            int gr = rowbase + k;
            int flip = 0;
            if (gr < 0)         { gr += 128; flip = 128; }
            else if (gr >= 128) { gr -= 128; flip = 128; }
            const float* srow = x0g + gr * 256;
            float* erow = E + k * EP;
            for (int c = lane; c < 267; c += 32)
                erow[c] = srow[((c - 5) & 255) ^ flip];
            __syncwarp();
            rowconv_inplace(erow, lane);
        }
        __syncthreads();

        {
            const int cg = tid & 63;          // float4 col group
            const int rs = (tid >> 6) * 4;    // rows [rs, rs+4)
            float4 acc0 = {0,0,0,0}, acc1 = {0,0,0,0};
            float4 acc2 = {0,0,0,0}, acc3 = {0,0,0,0};
            #pragma unroll
            for (int k = 0; k < 15; ++k) {
                const float4 v = *(const float4*)(E + (rs + k) * EP + 4 * cg);
                if (k <= 11)           acc0 = f4fma(FILT[k],     v, acc0);
                if (k >= 1 && k <= 12) acc1 = f4fma(FILT[k - 1], v, acc1);
                if (k >= 2 && k <= 13) acc2 = f4fma(FILT[k - 2], v, acc2);
                if (k >= 3)            acc3 = f4fma(FILT[k - 3], v, acc3);
            }
            const int gi = 64 * h + rs;
            #pragma unroll
            for (int r = 0; r < 4; ++r) {
                const float4 x = *(const float4*)(x1g + (gi + r) * 256 + 4 * cg);
                const float4 a = (r == 0) ? acc0 : (r == 1) ? acc1
                               : (r == 2) ? acc2 : acc3;
                float4 o;
                o.x = -INV_SQRT2 * (x.x + a.x);
                o.y = -INV_SQRT2 * (x.y + a.y);
                o.z = -INV_SQRT2 * (x.z + a.z);
                o.w = -INV_SQRT2 * (x.w + a.w);
                *(float4*)(Q1 + (rs + r) * QP + 4 * cg) = o;
            }
        }
    }

    CLUSTER_SYNC();     // own+peer Q1 complete before halo reads

    // ==== phase 2: Q0 = sqrt2*x0 + sefilter(Q1, off=6) ====================
    {
        const int rowbase = 64 * h - 6;
        for (int k = wrp; k < 75; k += 32) {
            int gr = rowbase + k;
            int flip = 0;
            if (gr < 0)         { gr += 128; flip = 128; }
            else if (gr >= 128) { gr -= 128; flip = 128; }
            const int owner = gr >> 6;        // warp-uniform
            const int lr    = gr & 63;
            float* erow = E + k * EP;
            if (owner == h) {
                const float* qrow = Q1 + lr * QP;
                for (int c = lane; c < 267; c += 32)
                    erow[c] = qrow[((c - 6) & 255) ^ flip];
            } else {
                const uint32_t pb = q1PeerBase + (uint32_t)(lr * QP) * 4u;
                for (int c = lane; c < 267; c += 32)
                    erow[c] = ld_dsm(pb + (uint32_t)(((c - 6) & 255) ^ flip) * 4u);
            }
            __syncwarp();
            rowconv_inplace(erow, lane);
        }
        __syncthreads();

        {
            const int cg = tid & 63;
            const int rs = (tid >> 6) * 4;
            float4 acc0 = {0,0,0,0}, acc1 = {0,0,0,0};
            float4 acc2 = {0,0,0,0}, acc3 = {0,0,0,0};
            #pragma unroll
            for (int k = 0; k < 15; ++k) {
                const float4 v = *(const float4*)(E + (rs + k) * EP + 4 * cg);
                if (k <= 11)           acc0 = f4fma(FILT[k],     v, acc0);
                if (k >= 1 && k <= 12) acc1 = f4fma(FILT[k - 1], v, acc1);
                if (k >= 2 && k <= 13) acc2 = f4fma(FILT[k - 2], v, acc2);
                if (k >= 3)            acc3 = f4fma(FILT[k - 3], v, acc3);
            }
            const int gi = 64 * h + rs;
            #pragma unroll
            for (int r = 0; r < 4; ++r) {
                const float4 x = *(const float4*)(x0g + (gi + r) * 256 + 4 * cg);
                const float4 a = (r == 0) ? acc0 : (r == 1) ? acc1
                               : (r == 2) ? acc2 : acc3;
                float4 o;
                o.x = SQRT2 * x.x + a.x;
                o.y = SQRT2 * x.y + a.y;
                o.z = SQRT2 * x.z + a.z;
                o.w = SQRT2 * x.w + a.w;
                *(float4*)(Q0 + (rs + r) * QP + 4 * cg) = o;
            }
        }
        __syncthreads();
    }

    // ==== phase 3: qprec '1r' scatter — local rows only, bank-free ========
    {
        float* og = out + img2 * 65536;
        const int base128 = 128 * h;
        #pragma unroll
        for (int p = 0; p < 4; ++p) {
            const int row = base128 + 32 * p + lane;
            const int r   = row >> 1;
            const int lr  = (32 * p + lane) >> 1;
            const float* src = (lane & 1) ? (Q1 + lr * QP) : (Q0 + lr * QP);
            const int coff = (lane & 1) ? (-1 - r) : (-r);
            #pragma unroll
            for (int ui = 0; ui < 8; ++ui) {
                const int u = (wrp << 3) + ui;
                const int j = (base128 - u + 32 * p + lane) & 255;
                og[u * 256 + j] = src[(j + coff) & 255];
            }
        }
    }

    CLUSTER_SYNC();     // smem must outlive peer's phase-2 reads
}

// ---------------------------------------------------------------------------

extern "C" void kernel_launch(void* const* d_in, const int* in_sizes, int n_in,
                              void* d_out, int out_size)
{
    const float* y0 = (const float*)d_in[0];
    const float* y1 = (const float*)d_in[1];
    const float* y2 = (const float*)d_in[2];
    const float* y3 = (const float*)d_in[3];

    static bool once = []() {
        cudaFuncSetAttribute(stageA_kernel,
                             cudaFuncAttributeMaxDynamicSharedMemorySize,
                             3 * 128 * P1 * 4);
        cudaFuncSetAttribute(stageB_fused,
                             cudaFuncAttributeMaxDynamicSharedMemorySize,
                             SMB_BYTES);
        return true;
    }();
    (void)once;

    stageA_kernel<<<512, 1024, 3 * 128 * P1 * 4>>>(y0, y1, y2, y3);
    stageB_fused<<<512, 1024, SMB_BYTES>>>((float*)d_out);
}

// round 11
// speedup vs baseline: 1.0687x; 1.0687x over previous
#include <cuda_runtime.h>
#include <cstdint>

// ---------------------------------------------------------------------------
// ContourRec: 2-level contourlet DFB reconstruction (4 subbands).
// Stage A (fbrec '2c','per'): fused per-image kernel — proven R6/R8 config
//   (512 thr, P1=130). DO NOT TOUCH (1024-thr variants regressed twice).
// Stage B (fbrec '1r','qper_col') + qprec '1r': fused 2-CTA-cluster kernel,
//   1024 thr. R10: row conv loads its 24-float window DIRECTLY from the
//   source (gmem x0 / smem Q1) — E staging pass removed; E holds only the
//   row-conv output. Wrap XOR (^128) preserves float4 contiguity/alignment.
// ---------------------------------------------------------------------------

#define P1 130
#define INV_SQRT2 0.70710678118654752f
#define SQRT2     1.41421356237309505f

__device__ float g_x[16777216];     // 8*64*128*256 (stage-A output)

#define DEF_FILT const float FILT[12] = {0.0144f, 0.0272f, 0.0526f, 0.0972f, \
    0.193f, 0.63f, -0.63f, -0.193f, -0.0972f, -0.0526f, -0.0272f, -0.0144f}

// ---------------- Stage A: fused per-image kernel (512 thr, R6) ------------

__device__ __forceinline__ void hconvA(const float* __restrict__ S,
                                       float* __restrict__ D, int off, int tid)
{
    DEF_FILT;
    const int j  = tid & 127;
    const int i0 = (tid >> 7) * 32;
    #pragma unroll
    for (int ck = 0; ck < 2; ++ck) {
        const int ib = i0 + 16 * ck - off;
        float buf[27];
        #pragma unroll
        for (int k = 0; k < 27; ++k) buf[k] = S[((ib + k) & 127) * P1 + j];
        #pragma unroll
        for (int r = 0; r < 16; ++r) {
            float acc = 0.f;
            #pragma unroll
            for (int t = 0; t < 12; ++t) acc = fmaf(FILT[t], buf[r + t], acc);
            D[(i0 + 16 * ck + r) * P1 + j] = acc;
        }
    }
}

template <bool COMBINE>
__device__ __forceinline__ void wconvA(const float* __restrict__ S,
                                       float* __restrict__ D, int off, int tid)
{
    DEF_FILT;
    const int i  = tid & 127;
    const int j0 = (tid >> 7) * 32;
    const float* row = S + i * P1;
    #pragma unroll
    for (int ck = 0; ck < 2; ++ck) {
        const int jb = j0 + 16 * ck - off;
        float buf[27];
        #pragma unroll
        for (int k = 0; k < 27; ++k) buf[k] = row[(jb + k) & 127];
        #pragma unroll
        for (int r = 0; r < 16; ++r) {
            float acc = 0.f;
            #pragma unroll
            for (int t = 0; t < 12; ++t) acc = fmaf(FILT[t], buf[r + t], acc);
            const int o = i * P1 + j0 + 16 * ck + r;
            if (COMBINE) D[o] = SQRT2 * D[o] + acc;
            else         D[o] = acc;
        }
    }
}

__global__ __launch_bounds__(512) void stageA_kernel(
    const float* __restrict__ y0, const float* __restrict__ y1,
    const float* __restrict__ y2, const float* __restrict__ y3)
{
    extern __shared__ float sm[];
    float* A = sm;
    float* B = sm + 128 * P1;
    float* C = sm + 2 * 128 * P1;

    const int img = blockIdx.x;
    const int b = img >> 6, ch = img & 63;
    const float* gY0;
    const float* gY1;
    if (ch < 32) { gY0 = y1 + (b * 32 + ch) * 16384;
                   gY1 = y0 + (b * 32 + ch) * 16384; }
    else         { gY0 = y2 + (b * 32 + ch - 32) * 16384;
                   gY1 = y3 + (b * 32 + ch - 32) * 16384; }

    const int tid = threadIdx.x;

    for (int idx = tid; idx < 16384; idx += 512)
        A[(idx >> 7) * P1 + (idx & 127)] = gY0[idx];
    __syncthreads();

    hconvA(A, B, 5, tid);
    __syncthreads();
    wconvA<false>(B, C, 5, tid);
    __syncthreads();

    for (int idx = tid; idx < 16384; idx += 512) {
        const int o = (idx >> 7) * P1 + (idx & 127);
        C[o] = -INV_SQRT2 * (gY1[idx] + C[o]);
    }
    __syncthreads();

    hconvA(C, B, 6, tid);
    __syncthreads();
    wconvA<true>(B, A, 6, tid);
    __syncthreads();

    float* gx = g_x + img * 32768;
    for (int idx = tid; idx < 32768; idx += 512) {
        const int i = idx >> 8, j = idx & 255;
        const int col = (i + j) & 255;
        const int h = col >> 1;
        float v;
        if (col & 1) v = C[((i - 1 - h) & 127) * P1 + h];
        else         v = A[((i - h) & 127) * P1 + h];
        gx[idx] = v;
    }
}

// ---------------- Fused Stage B + qprec (2-CTA cluster, 1024 thr) ----------

#define QP  264                     // q pitch: bank-free phase-3 reads
#define EP  268                     // 16B-aligned rows
#define Q0OFF 0                     // Q0: 64 x 264
#define Q1OFF 16912                 // 64*264 + 16 -> Q1 banks complement Q0's
#define EOFF  33824                 // E: 75 x 268 (rowconv output, cols 0..255)
#define SMB_FLOATS (33824 + 75 * 268)
#define SMB_BYTES (SMB_FLOATS * 4)  // 215,696 B

__device__ __forceinline__ uint32_t smem_u32(const void* p) {
    uint32_t a;
    asm("{ .reg .u64 t; cvta.to.shared.u64 t, %1; cvt.u32.u64 %0, t; }"
        : "=r"(a) : "l"(p));
    return a;
}
__device__ __forceinline__ uint32_t mapa_rank(uint32_t addr, uint32_t rank) {
    uint32_t r;
    asm("mapa.shared::cluster.u32 %0, %1, %2;" : "=r"(r) : "r"(addr), "r"(rank));
    return r;
}
__device__ __forceinline__ float ld_dsm(uint32_t addr) {
    float v;
    asm volatile("ld.shared::cluster.f32 %0, [%1];" : "=f"(v) : "r"(addr));
    return v;
}
#define CLUSTER_SYNC() do { \
    asm volatile("barrier.cluster.arrive.aligned;" ::: "memory"); \
    asm volatile("barrier.cluster.wait.aligned;"  ::: "memory"); } while (0)

__device__ __forceinline__ float4 f4fma(float s, float4 v, float4 a) {
    a.x = fmaf(s, v.x, a.x); a.y = fmaf(s, v.y, a.y);
    a.z = fmaf(s, v.z, a.z); a.w = fmaf(s, v.w, a.w);
    return a;
}

// Convolve a 24-float register window: out[m] = sum_u FILT[u]*w[m+u+woff],
// m in [0,8); store 2x float4 to erow + 8*lane.
__device__ __forceinline__ void conv_store(const float* w, int woff,
                                           float* __restrict__ erow, int lane)
{
    DEF_FILT;
    float acc[8];
    #pragma unroll
    for (int m = 0; m < 8; ++m) acc[m] = 0.f;
    #pragma unroll
    for (int u = 0; u < 12; ++u) {
        const float fv = FILT[u];
        #pragma unroll
        for (int m = 0; m < 8; ++m)
            acc[m] = fmaf(fv, w[m + u + woff], acc[m]);
    }
    float4 o0, o1;
    o0.x=acc[0]; o0.y=acc[1]; o0.z=acc[2]; o0.w=acc[3];
    o1.x=acc[4]; o1.y=acc[5]; o1.z=acc[6]; o1.w=acc[7];
    *(float4*)(erow + 8 * lane)     = o0;
    *(float4*)(erow + 8 * lane + 4) = o1;
}

__global__ __launch_bounds__(1024) __cluster_dims__(2, 1, 1)
void stageB_fused(float* __restrict__ out)
{
    extern __shared__ float smB[];
    float* Q0 = smB + Q0OFF;
    float* Q1 = smB + Q1OFF;
    float* E  = smB + EOFF;

    const int tid  = threadIdx.x;
    const int lane = tid & 31;
    const int wrp  = tid >> 5;                // 0..31
    uint32_t hr;
    asm("mov.u32 %0, %%cluster_ctarank;" : "=r"(hr));
    const int h    = (int)hr;
    const int img2 = blockIdx.x >> 1;
    const int x0base = ((img2 >> 5) * 64 + (img2 & 31)) * 32768;
    const float* x0g = g_x + x0base;
    const float* x1g = x0g + 32 * 32768;

    const uint32_t q1PeerBase = mapa_rank(smem_u32(Q1), hr ^ 1u);

    DEF_FILT;

    // ==== phase 1: rowconv(x0, off 5) -> E; then vconv+combine -> Q1 ======
    {
        const int rowbase = 64 * h - 5;
        for (int k = wrp; k < 75; k += 32) {
            int gr = rowbase + k;
            int flip = 0;
            if (gr < 0)         { gr += 128; flip = 128; }
            else if (gr >= 128) { gr -= 128; flip = 128; }
            const float* srow = x0g + gr * 256;
            float* erow = E + k * EP;
            // window: out col 8L+m needs src[((8L+m+u-5)&255)^flip]
            float w[24];
            if (lane >= 1 && lane <= 30) {
                const int b = 8 * lane - 8;       // cols b..b+23, all in [0,255]
                #pragma unroll
                for (int v = 0; v < 6; ++v) {
                    const float4 t = *(const float4*)(srow + ((b + 4 * v) ^ flip));
                    w[4*v+0]=t.x; w[4*v+1]=t.y; w[4*v+2]=t.z; w[4*v+3]=t.w;
                }
            } else {
                #pragma unroll
                for (int m = 0; m < 19; ++m)
                    w[m + 3] = srow[((8 * lane + m - 5) & 255) ^ flip];
            }
            conv_store(w, 3, erow, lane);         // w[m+u+3] = col 8L+m+u-5
        }
        __syncthreads();

        {
            const int cg = tid & 63;          // float4 col group
            const int rs = (tid >> 6) * 4;    // rows [rs, rs+4)
            float4 acc0 = {0,0,0,0}, acc1 = {0,0,0,0};
            float4 acc2 = {0,0,0,0}, acc3 = {0,0,0,0};
            #pragma unroll
            for (int k = 0; k < 15; ++k) {
                const float4 v = *(const float4*)(E + (rs + k) * EP + 4 * cg);
                if (k <= 11)           acc0 = f4fma(FILT[k],     v, acc0);
                if (k >= 1 && k <= 12) acc1 = f4fma(FILT[k - 1], v, acc1);
                if (k >= 2 && k <= 13) acc2 = f4fma(FILT[k - 2], v, acc2);
                if (k >= 3)            acc3 = f4fma(FILT[k - 3], v, acc3);
            }
            const int gi = 64 * h + rs;
            #pragma unroll
            for (int r = 0; r < 4; ++r) {
                const float4 x = *(const float4*)(x1g + (gi + r) * 256 + 4 * cg);
                const float4 a = (r == 0) ? acc0 : (r == 1) ? acc1
                               : (r == 2) ? acc2 : acc3;
                float4 o;
                o.x = -INV_SQRT2 * (x.x + a.x);
                o.y = -INV_SQRT2 * (x.y + a.y);
                o.z = -INV_SQRT2 * (x.z + a.z);
                o.w = -INV_SQRT2 * (x.w + a.w);
                *(float4*)(Q1 + (rs + r) * QP + 4 * cg) = o;
            }
        }
    }

    CLUSTER_SYNC();     // own+peer Q1 complete before halo reads

    // ==== phase 2: rowconv(Q1, off 6) -> E; then vconv+combine -> Q0 ======
    {
        const int rowbase = 64 * h - 6;
        for (int k = wrp; k < 75; k += 32) {
            int gr = rowbase + k;
            int flip = 0;
            if (gr < 0)         { gr += 128; flip = 128; }
            else if (gr >= 128) { gr -= 128; flip = 128; }
            const int owner = gr >> 6;        // warp-uniform
            const int lr    = gr & 63;
            float* erow = E + k * EP;
            // window: out col 8L+m needs q1[((8L+m+u-6)&255)^flip]
            float w[24];
            if (owner == h) {
                const float* qrow = Q1 + lr * QP;
                if (lane >= 1 && lane <= 30) {
                    const int b = 8 * lane - 8;   // cols b..b+23 in [0,255]
                    #pragma unroll
                    for (int v = 0; v < 6; ++v) {
                        const float4 t = *(const float4*)(qrow + ((b + 4 * v) ^ flip));
                        w[4*v+0]=t.x; w[4*v+1]=t.y; w[4*v+2]=t.z; w[4*v+3]=t.w;
                    }
                } else {
                    #pragma unroll
                    for (int m = 0; m < 19; ++m)
                        w[m + 2] = qrow[((8 * lane + m - 6) & 255) ^ flip];
                }
            } else {
                const uint32_t pb = q1PeerBase + (uint32_t)(lr * QP) * 4u;
                #pragma unroll
                for (int m = 0; m < 19; ++m)
                    w[m + 2] = ld_dsm(pb +
                        (uint32_t)(((8 * lane + m - 6) & 255) ^ flip) * 4u);
            }
            conv_store(w, 2, erow, lane);         // w[m+u+2] = col 8L+m+u-6
        }
        __syncthreads();

        {
            const int cg = tid & 63;
            const int rs = (tid >> 6) * 4;
            float4 acc0 = {0,0,0,0}, acc1 = {0,0,0,0};
            float4 acc2 = {0,0,0,0}, acc3 = {0,0,0,0};
            #pragma unroll
            for (int k = 0; k < 15; ++k) {
                const float4 v = *(const float4*)(E + (rs + k) * EP + 4 * cg);
                if (k <= 11)           acc0 = f4fma(FILT[k],     v, acc0);
                if (k >= 1 && k <= 12) acc1 = f4fma(FILT[k - 1], v, acc1);
                if (k >= 2 && k <= 13) acc2 = f4fma(FILT[k - 2], v, acc2);
                if (k >= 3)            acc3 = f4fma(FILT[k - 3], v, acc3);
            }
            const int gi = 64 * h + rs;
            #pragma unroll
            for (int r = 0; r < 4; ++r) {
                const float4 x = *(const float4*)(x0g + (gi + r) * 256 + 4 * cg);
                const float4 a = (r == 0) ? acc0 : (r == 1) ? acc1
                               : (r == 2) ? acc2 : acc3;
                float4 o;
                o.x = SQRT2 * x.x + a.x;
                o.y = SQRT2 * x.y + a.y;
                o.z = SQRT2 * x.z + a.z;
                o.w = SQRT2 * x.w + a.w;
                *(float4*)(Q0 + (rs + r) * QP + 4 * cg) = o;
            }
        }
        __syncthreads();
    }

    // ==== phase 3: qprec '1r' scatter — local rows only, bank-free ========
    {
        float* og = out + img2 * 65536;
        const int base128 = 128 * h;
        #pragma unroll
        for (int p = 0; p < 4; ++p) {
            const int row = base128 + 32 * p + lane;
            const int r   = row >> 1;
            const int lr  = (32 * p + lane) >> 1;
            const float* src = (lane & 1) ? (Q1 + lr * QP) : (Q0 + lr * QP);
            const int coff = (lane & 1) ? (-1 - r) : (-r);
            #pragma unroll
            for (int ui = 0; ui < 8; ++ui) {
                const int u = (wrp << 3) + ui;
                const int j = (base128 - u + 32 * p + lane) & 255;
                og[u * 256 + j] = src[(j + coff) & 255];
            }
        }
    }

    CLUSTER_SYNC();     // smem must outlive peer's phase-2 reads
}

// ---------------------------------------------------------------------------

extern "C" void kernel_launch(void* const* d_in, const int* in_sizes, int n_in,
                              void* d_out, int out_size)
{
    const float* y0 = (const float*)d_in[0];
    const float* y1 = (const float*)d_in[1];
    const float* y2 = (const float*)d_in[2];
    const float* y3 = (const float*)d_in[3];

    static bool once = []() {
        cudaFuncSetAttribute(stageA_kernel,
                             cudaFuncAttributeMaxDynamicSharedMemorySize,
                             3 * 128 * P1 * 4);
        cudaFuncSetAttribute(stageB_fused,
                             cudaFuncAttributeMaxDynamicSharedMemorySize,
                             SMB_BYTES);
        return true;
    }();
    (void)once;

    stageA_kernel<<<512, 512, 3 * 128 * P1 * 4>>>(y0, y1, y2, y3);
    stageB_fused<<<512, 1024, SMB_BYTES>>>((float*)d_out);
}

// round 12
// speedup vs baseline: 1.1998x; 1.1227x over previous
#include <cuda_runtime.h>
#include <cstdint>

// ---------------------------------------------------------------------------
// ContourRec: 2-level contourlet DFB reconstruction (4 subbands).
// Stage A (fbrec '2c','per'): fused per-image kernel, 512 thr, R12 float4
//   structure (rowconv register windows + colconv tap accumulation) — ported
//   from the proven R8 stageB design. PA=132.
// Stage B (fbrec '1r','qper_col') + qprec '1r': EXACT R8 version (75.7us) —
//   R10's direct-load variant regressed (LDG amplification); reverted.
// ---------------------------------------------------------------------------

#define PA 132
#define INV_SQRT2 0.70710678118654752f
#define SQRT2     1.41421356237309505f

__device__ float g_x[16777216];     // 8*64*128*256 (stage-A output)

#define DEF_FILT const float FILT[12] = {0.0144f, 0.0272f, 0.0526f, 0.0972f, \
    0.193f, 0.63f, -0.63f, -0.193f, -0.0972f, -0.0526f, -0.0272f, -0.0144f}

__device__ __forceinline__ float4 f4fma(float s, float4 v, float4 a) {
    a.x = fmaf(s, v.x, a.x); a.y = fmaf(s, v.y, a.y);
    a.z = fmaf(s, v.z, a.z); a.w = fmaf(s, v.w, a.w);
    return a;
}

// ---------------- Stage A: fused per-image kernel (512 thr, float4) --------
// smem: A (Y0 -> p0), B (rowconv scratch), C (p1): 3*128*132*4 = 202,752 B.

// out[m] = sum_u FILT[u] * w[m+u+woff], m in [0,8); 2x STS.128.
__device__ __forceinline__ void convA_store(const float* w, int woff,
                                            float* __restrict__ drow, int s)
{
    DEF_FILT;
    float acc[8];
    #pragma unroll
    for (int m = 0; m < 8; ++m) acc[m] = 0.f;
    #pragma unroll
    for (int u = 0; u < 12; ++u) {
        const float fv = FILT[u];
        #pragma unroll
        for (int m = 0; m < 8; ++m)
            acc[m] = fmaf(fv, w[m + u + woff], acc[m]);
    }
    float4 o0, o1;
    o0.x=acc[0]; o0.y=acc[1]; o0.z=acc[2]; o0.w=acc[3];
    o1.x=acc[4]; o1.y=acc[5]; o1.z=acc[6]; o1.w=acc[7];
    *(float4*)(drow + 8 * s)     = o0;
    *(float4*)(drow + 8 * s + 4) = o1;
}

// Rowconv: D[r][c] = sum_u FILT[u] * S[r][(c+u-off)&127], all 128 rows.
// Warp = 2 rows; lane s=lane&15 owns cols [8s, 8s+8).
template <int OFF>
__device__ __forceinline__ void rowconvA(const float* __restrict__ S,
                                         float* __restrict__ D,
                                         int wrp, int lane)
{
    const int s    = lane & 15;
    const int half = lane >> 4;
    #pragma unroll
    for (int pass = 0; pass < 4; ++pass) {
        const int r = pass * 32 + wrp * 2 + half;
        const float* srow = S + r * PA;
        float w[24];
        if (s >= 1 && s <= 14) {
            const int b = 8 * s - 8;              // cols b..b+23 in [0,127]
            #pragma unroll
            for (int v = 0; v < 6; ++v) {
                const float4 t = *(const float4*)(srow + b + 4 * v);
                w[4*v+0]=t.x; w[4*v+1]=t.y; w[4*v+2]=t.z; w[4*v+3]=t.w;
            }
        } else {
            #pragma unroll
            for (int q = 0; q < 19; ++q)
                w[q + (8 - OFF)] = srow[(8 * s + q - OFF) & 127];
        }
        convA_store(w, 8 - OFF, D + r * PA, s);   // w[m+u+8-OFF] = col 8s+m+u-OFF
    }
}

// Colconv + epilogue. MODE 0: C = -1/sqrt2*(Y1g + conv(S));
//                     MODE 1: A = sqrt2*A + conv(S).
template <int OFF, int MODE>
__device__ __forceinline__ void colconvA(const float* __restrict__ S,
                                         float* __restrict__ Dst,
                                         const float* __restrict__ gY1,
                                         int tid)
{
    DEF_FILT;
    const int cg = tid & 31;                      // float4 col group
    const int rs = (tid >> 5) * 8;                // rows [rs, rs+8)
    float4 acc[8];
    #pragma unroll
    for (int r = 0; r < 8; ++r) acc[r] = make_float4(0.f, 0.f, 0.f, 0.f);
    #pragma unroll
    for (int kk = 0; kk < 19; ++kk) {
        const float4 v = *(const float4*)(S + ((rs + kk - OFF) & 127) * PA + 4 * cg);
        #pragma unroll
        for (int r = 0; r < 8; ++r)
            if (r <= kk && kk - r < 12)
                acc[r] = f4fma(FILT[kk - r], v, acc[r]);
    }
    #pragma unroll
    for (int r = 0; r < 8; ++r) {
        float* d = Dst + (rs + r) * PA + 4 * cg;
        float4 o;
        if (MODE == 0) {
            const float4 x = *(const float4*)(gY1 + (rs + r) * 128 + 4 * cg);
            o.x = -INV_SQRT2 * (x.x + acc[r].x);
            o.y = -INV_SQRT2 * (x.y + acc[r].y);
            o.z = -INV_SQRT2 * (x.z + acc[r].z);
            o.w = -INV_SQRT2 * (x.w + acc[r].w);
        } else {
            const float4 x = *(const float4*)d;
            o.x = SQRT2 * x.x + acc[r].x;
            o.y = SQRT2 * x.y + acc[r].y;
            o.z = SQRT2 * x.z + acc[r].z;
            o.w = SQRT2 * x.w + acc[r].w;
        }
        *(float4*)d = o;
    }
}

__global__ __launch_bounds__(512) void stageA_kernel(
    const float* __restrict__ y0, const float* __restrict__ y1,
    const float* __restrict__ y2, const float* __restrict__ y3)
{
    extern __shared__ float sm[];
    float* A = sm;                      // Y0 -> p0
    float* B = sm + 128 * PA;           // rowconv scratch
    float* C = sm + 2 * 128 * PA;       // p1

    const int img = blockIdx.x;
    const int b = img >> 6, ch = img & 63;
    const float* gY0;
    const float* gY1;
    if (ch < 32) { gY0 = y1 + (b * 32 + ch) * 16384;
                   gY1 = y0 + (b * 32 + ch) * 16384; }
    else         { gY0 = y2 + (b * 32 + ch - 32) * 16384;
                   gY1 = y3 + (b * 32 + ch - 32) * 16384; }

    const int tid  = threadIdx.x;
    const int lane = tid & 31;
    const int wrp  = tid >> 5;          // 0..15

    // load Y0 (float4, coalesced)
    for (int idx = tid; idx < 4096; idx += 512) {
        const int i = idx >> 5, g = idx & 31;
        *(float4*)(A + i * PA + 4 * g) = *(const float4*)(gY0 + i * 128 + 4 * g);
    }
    __syncthreads();

    rowconvA<5>(A, B, wrp, lane);       // B = rowconv(Y0)
    __syncthreads();
    colconvA<5, 0>(B, C, gY1, tid);     // C = p1 = -1/sqrt2 (Y1 + sefilter(Y0))
    __syncthreads();

    rowconvA<6>(C, B, wrp, lane);       // B = rowconv(p1), shift (1,1)
    __syncthreads();
    colconvA<6, 1>(B, A, nullptr, tid); // A = p0 = sqrt2*Y0 + colconv(B)
    __syncthreads();

    // qprec '2c': x[i,j]; col=(i+j)%256
    float* gx = g_x + img * 32768;
    for (int idx = tid; idx < 32768; idx += 512) {
        const int i = idx >> 8, j = idx & 255;
        const int col = (i + j) & 255;
        const int hh = col >> 1;
        float v;
        if (col & 1) v = C[((i - 1 - hh) & 127) * PA + hh];
        else         v = A[((i - hh) & 127) * PA + hh];
        gx[idx] = v;
    }
}

// ---------------- Fused Stage B + qprec (2-CTA cluster, 1024 thr) ----------
// EXACT R8 version (75.7us).

#define QP  264                     // q pitch: bank-free phase-3 reads
#define EP  268                     // 16B-aligned rows
#define Q0OFF 0                     // Q0: 64 x 264
#define Q1OFF 16912                 // 64*264 + 16 -> Q1 banks complement Q0's
#define EOFF  33824                 // E: 75 x 268 (16B aligned)
#define SMB_FLOATS (33824 + 75 * 268)
#define SMB_BYTES (SMB_FLOATS * 4)  // 215,696 B

__device__ __forceinline__ uint32_t smem_u32(const void* p) {
    uint32_t a;
    asm("{ .reg .u64 t; cvta.to.shared.u64 t, %1; cvt.u32.u64 %0, t; }"
        : "=r"(a) : "l"(p));
    return a;
}
__device__ __forceinline__ uint32_t mapa_rank(uint32_t addr, uint32_t rank) {
    uint32_t r;
    asm("mapa.shared::cluster.u32 %0, %1, %2;" : "=r"(r) : "r"(addr), "r"(rank));
    return r;
}
__device__ __forceinline__ float ld_dsm(uint32_t addr) {
    float v;
    asm volatile("ld.shared::cluster.f32 %0, [%1];" : "=f"(v) : "r"(addr));
    return v;
}
#define CLUSTER_SYNC() do { \
    asm volatile("barrier.cluster.arrive.aligned;" ::: "memory"); \
    asm volatile("barrier.cluster.wait.aligned;"  ::: "memory"); } while (0)

// In-place row conv on E row k: out[c] = sum_u FILT[u]*Ein[c+u], c in [0,256).
__device__ __forceinline__ void rowconv_inplace(float* __restrict__ erow,
                                                int lane)
{
    DEF_FILT;
    const float* tr = erow + 8 * lane;
    float w[20];
    const float4 a0 = *(const float4*)(tr);
    const float4 a1 = *(const float4*)(tr + 4);
    const float4 a2 = *(const float4*)(tr + 8);
    const float4 a3 = *(const float4*)(tr + 12);
    const float4 a4 = *(const float4*)(tr + 16);
    w[0]=a0.x; w[1]=a0.y; w[2]=a0.z; w[3]=a0.w;
    w[4]=a1.x; w[5]=a1.y; w[6]=a1.z; w[7]=a1.w;
    w[8]=a2.x; w[9]=a2.y; w[10]=a2.z; w[11]=a2.w;
    w[12]=a3.x; w[13]=a3.y; w[14]=a3.z; w[15]=a3.w;
    w[16]=a4.x; w[17]=a4.y; w[18]=a4.z; w[19]=a4.w;
    float acc[8];
    #pragma unroll
    for (int m = 0; m < 8; ++m) acc[m] = 0.f;
    #pragma unroll
    for (int u = 0; u < 12; ++u) {
        const float fv = FILT[u];
        #pragma unroll
        for (int m = 0; m < 8; ++m)
            acc[m] = fmaf(fv, w[m + u], acc[m]);
    }
    __syncwarp();
    float4 o0, o1;
    o0.x=acc[0]; o0.y=acc[1]; o0.z=acc[2]; o0.w=acc[3];
    o1.x=acc[4]; o1.y=acc[5]; o1.z=acc[6]; o1.w=acc[7];
    *(float4*)(erow + 8 * lane)     = o0;
    *(float4*)(erow + 8 * lane + 4) = o1;
}

__global__ __launch_bounds__(1024) __cluster_dims__(2, 1, 1)
void stageB_fused(float* __restrict__ out)
{
    extern __shared__ float smB[];
    float* Q0 = smB + Q0OFF;
    float* Q1 = smB + Q1OFF;
    float* E  = smB + EOFF;

    const int tid  = threadIdx.x;
    const int lane = tid & 31;
    const int wrp  = tid >> 5;                // 0..31
    uint32_t hr;
    asm("mov.u32 %0, %%cluster_ctarank;" : "=r"(hr));
    const int h    = (int)hr;
    const int img2 = blockIdx.x >> 1;
    const int x0base = ((img2 >> 5) * 64 + (img2 & 31)) * 32768;
    const float* x0g = g_x + x0base;
    const float* x1g = x0g + 32 * 32768;

    const uint32_t q1PeerBase = mapa_rank(smem_u32(Q1), hr ^ 1u);

    DEF_FILT;

    // ==== phase 1: Q1 = -1/sqrt2 (x1 + sefilter(x0, off=5)) ===============
    {
        const int rowbase = 64 * h - 5;
        for (int k = wrp; k < 75; k += 32) {
            int gr = rowbase + k;
            int flip = 0;
            if (gr < 0)         { gr += 128; flip = 128; }
            else if (gr >= 128) { gr -= 128; flip = 128; }
            const float* srow = x0g + gr * 256;
            float* erow = E + k * EP;
            for (int c = lane; c < 267; c += 32)
                erow[c] = srow[((c - 5) & 255) ^ flip];
            __syncwarp();
            rowconv_inplace(erow, lane);
        }
        __syncthreads();

        {
            const int cg = tid & 63;          // float4 col group
            const int rs = (tid >> 6) * 4;    // rows [rs, rs+4)
            float4 acc0 = {0,0,0,0}, acc1 = {0,0,0,0};
            float4 acc2 = {0,0,0,0}, acc3 = {0,0,0,0};
            #pragma unroll
            for (int k = 0; k < 15; ++k) {
                const float4 v = *(const float4*)(E + (rs + k) * EP + 4 * cg);
                if (k <= 11)           acc0 = f4fma(FILT[k],     v, acc0);
                if (k >= 1 && k <= 12) acc1 = f4fma(FILT[k - 1], v, acc1);
                if (k >= 2 && k <= 13) acc2 = f4fma(FILT[k - 2], v, acc2);
                if (k >= 3)            acc3 = f4fma(FILT[k - 3], v, acc3);
            }
            const int gi = 64 * h + rs;
            #pragma unroll
            for (int r = 0; r < 4; ++r) {
                const float4 x = *(const float4*)(x1g + (gi + r) * 256 + 4 * cg);
                const float4 a = (r == 0) ? acc0 : (r == 1) ? acc1
                               : (r == 2) ? acc2 : acc3;
                float4 o;
                o.x = -INV_SQRT2 * (x.x + a.x);
                o.y = -INV_SQRT2 * (x.y + a.y);
                o.z = -INV_SQRT2 * (x.z + a.z);
                o.w = -INV_SQRT2 * (x.w + a.w);
                *(float4*)(Q1 + (rs + r) * QP + 4 * cg) = o;
            }
        }
    }

    CLUSTER_SYNC();     // own+peer Q1 complete before halo reads

    // ==== phase 2: Q0 = sqrt2*x0 + sefilter(Q1, off=6) ====================
    {
        const int rowbase = 64 * h - 6;
        for (int k = wrp; k < 75; k += 32) {
            int gr = rowbase + k;
            int flip = 0;
            if (gr < 0)         { gr += 128; flip = 128; }
            else if (gr >= 128) { gr -= 128; flip = 128; }
            const int owner = gr >> 6;        // warp-uniform
            const int lr    = gr & 63;
            float* erow = E + k * EP;
            if (owner == h) {
                const float* qrow = Q1 + lr * QP;
                for (int c = lane; c < 267; c += 32)
                    erow[c] = qrow[((c - 6) & 255) ^ flip];
            } else {
                const uint32_t pb = q1PeerBase + (uint32_t)(lr * QP) * 4u;
                for (int c = lane; c < 267; c += 32)
                    erow[c] = ld_dsm(pb + (uint32_t)(((c - 6) & 255) ^ flip) * 4u);
            }
            __syncwarp();
            rowconv_inplace(erow, lane);
        }
        __syncthreads();

        {
            const int cg = tid & 63;
            const int rs = (tid >> 6) * 4;
            float4 acc0 = {0,0,0,0}, acc1 = {0,0,0,0};
            float4 acc2 = {0,0,0,0}, acc3 = {0,0,0,0};
            #pragma unroll
            for (int k = 0; k < 15; ++k) {
                const float4 v = *(const float4*)(E + (rs + k) * EP + 4 * cg);
                if (k <= 11)           acc0 = f4fma(FILT[k],     v, acc0);
                if (k >= 1 && k <= 12) acc1 = f4fma(FILT[k - 1], v, acc1);
                if (k >= 2 && k <= 13) acc2 = f4fma(FILT[k - 2], v, acc2);
                if (k >= 3)            acc3 = f4fma(FILT[k - 3], v, acc3);
            }
            const int gi = 64 * h + rs;
            #pragma unroll
            for (int r = 0; r < 4; ++r) {
                const float4 x = *(const float4*)(x0g + (gi + r) * 256 + 4 * cg);
                const float4 a = (r == 0) ? acc0 : (r == 1) ? acc1
                               : (r == 2) ? acc2 : acc3;
                float4 o;
                o.x = SQRT2 * x.x + a.x;
                o.y = SQRT2 * x.y + a.y;
                o.z = SQRT2 * x.z + a.z;
                o.w = SQRT2 * x.w + a.w;
                *(float4*)(Q0 + (rs + r) * QP + 4 * cg) = o;
            }
        }
        __syncthreads();
    }

    // ==== phase 3: qprec '1r' scatter — local rows only, bank-free ========
    {
        float* og = out + img2 * 65536;
        const int base128 = 128 * h;
        #pragma unroll
        for (int p = 0; p < 4; ++p) {
            const int row = base128 + 32 * p + lane;
            const int r   = row >> 1;
            const int lr  = (32 * p + lane) >> 1;
            const float* src = (lane & 1) ? (Q1 + lr * QP) : (Q0 + lr * QP);
            const int coff = (lane & 1) ? (-1 - r) : (-r);
            #pragma unroll
            for (int ui = 0; ui < 8; ++ui) {
                const int u = (wrp << 3) + ui;
                const int j = (base128 - u + 32 * p + lane) & 255;
                og[u * 256 + j] = src[(j + coff) & 255];
            }
        }
    }

    CLUSTER_SYNC();     // smem must outlive peer's phase-2 reads
}

// ---------------------------------------------------------------------------

extern "C" void kernel_launch(void* const* d_in, const int* in_sizes, int n_in,
                              void* d_out, int out_size)
{
    const float* y0 = (const float*)d_in[0];
    const float* y1 = (const float*)d_in[1];
    const float* y2 = (const float*)d_in[2];
    const float* y3 = (const float*)d_in[3];

    static bool once = []() {
        cudaFuncSetAttribute(stageA_kernel,
                             cudaFuncAttributeMaxDynamicSharedMemorySize,
                             3 * 128 * PA * 4);
        cudaFuncSetAttribute(stageB_fused,
                             cudaFuncAttributeMaxDynamicSharedMemorySize,
                             SMB_BYTES);
        return true;
    }();
    (void)once;

    stageA_kernel<<<512, 512, 3 * 128 * PA * 4>>>(y0, y1, y2, y3);
    stageB_fused<<<512, 1024, SMB_BYTES>>>((float*)d_out);
}

// round 13
// speedup vs baseline: 1.2872x; 1.0729x over previous
#include <cuda_runtime.h>
#include <cstdint>

// ---------------------------------------------------------------------------
// ContourRec: 2-level contourlet DFB reconstruction (4 subbands).
// Stage A (fbrec '2c','per'): fused per-image kernel — R12 float4 (512 thr).
// Stage B (fbrec '1r','qper_col') + qprec '1r': fused 4-CTA-cluster kernel,
//   each CTA owns 32 rows of Q0/Q1 -> smem 113.7KB -> 2 CTAs/SM (100% occ).
//   __launch_bounds__(1024,2): 32-reg target; rowconv chunk-consumes window.
// ---------------------------------------------------------------------------

#define PA 132
#define INV_SQRT2 0.70710678118654752f
#define SQRT2     1.41421356237309505f

__device__ float g_x[16777216];     // 8*64*128*256 (stage-A output)

#define DEF_FILT const float FILT[12] = {0.0144f, 0.0272f, 0.0526f, 0.0972f, \
    0.193f, 0.63f, -0.63f, -0.193f, -0.0972f, -0.0526f, -0.0272f, -0.0144f}

__device__ __forceinline__ float4 f4fma(float s, float4 v, float4 a) {
    a.x = fmaf(s, v.x, a.x); a.y = fmaf(s, v.y, a.y);
    a.z = fmaf(s, v.z, a.z); a.w = fmaf(s, v.w, a.w);
    return a;
}

// ---------------- Stage A: fused per-image kernel (512 thr, R12) -----------

__device__ __forceinline__ void convA_store(const float* w, int woff,
                                            float* __restrict__ drow, int s)
{
    DEF_FILT;
    float acc[8];
    #pragma unroll
    for (int m = 0; m < 8; ++m) acc[m] = 0.f;
    #pragma unroll
    for (int u = 0; u < 12; ++u) {
        const float fv = FILT[u];
        #pragma unroll
        for (int m = 0; m < 8; ++m)
            acc[m] = fmaf(fv, w[m + u + woff], acc[m]);
    }
    float4 o0, o1;
    o0.x=acc[0]; o0.y=acc[1]; o0.z=acc[2]; o0.w=acc[3];
    o1.x=acc[4]; o1.y=acc[5]; o1.z=acc[6]; o1.w=acc[7];
    *(float4*)(drow + 8 * s)     = o0;
    *(float4*)(drow + 8 * s + 4) = o1;
}

template <int OFF>
__device__ __forceinline__ void rowconvA(const float* __restrict__ S,
                                         float* __restrict__ D,
                                         int wrp, int lane)
{
    const int s    = lane & 15;
    const int half = lane >> 4;
    #pragma unroll
    for (int pass = 0; pass < 4; ++pass) {
        const int r = pass * 32 + wrp * 2 + half;
        const float* srow = S + r * PA;
        float w[24];
        if (s >= 1 && s <= 14) {
            const int b = 8 * s - 8;
            #pragma unroll
            for (int v = 0; v < 6; ++v) {
                const float4 t = *(const float4*)(srow + b + 4 * v);
                w[4*v+0]=t.x; w[4*v+1]=t.y; w[4*v+2]=t.z; w[4*v+3]=t.w;
            }
        } else {
            #pragma unroll
            for (int q = 0; q < 19; ++q)
                w[q + (8 - OFF)] = srow[(8 * s + q - OFF) & 127];
        }
        convA_store(w, 8 - OFF, D + r * PA, s);
    }
}

template <int OFF, int MODE>
__device__ __forceinline__ void colconvA(const float* __restrict__ S,
                                         float* __restrict__ Dst,
                                         const float* __restrict__ gY1,
                                         int tid)
{
    DEF_FILT;
    const int cg = tid & 31;
    const int rs = (tid >> 5) * 8;
    float4 acc[8];
    #pragma unroll
    for (int r = 0; r < 8; ++r) acc[r] = make_float4(0.f, 0.f, 0.f, 0.f);
    #pragma unroll
    for (int kk = 0; kk < 19; ++kk) {
        const float4 v = *(const float4*)(S + ((rs + kk - OFF) & 127) * PA + 4 * cg);
        #pragma unroll
        for (int r = 0; r < 8; ++r)
            if (r <= kk && kk - r < 12)
                acc[r] = f4fma(FILT[kk - r], v, acc[r]);
    }
    #pragma unroll
    for (int r = 0; r < 8; ++r) {
        float* d = Dst + (rs + r) * PA + 4 * cg;
        float4 o;
        if (MODE == 0) {
            const float4 x = *(const float4*)(gY1 + (rs + r) * 128 + 4 * cg);
            o.x = -INV_SQRT2 * (x.x + acc[r].x);
            o.y = -INV_SQRT2 * (x.y + acc[r].y);
            o.z = -INV_SQRT2 * (x.z + acc[r].z);
            o.w = -INV_SQRT2 * (x.w + acc[r].w);
        } else {
            const float4 x = *(const float4*)d;
            o.x = SQRT2 * x.x + acc[r].x;
            o.y = SQRT2 * x.y + acc[r].y;
            o.z = SQRT2 * x.z + acc[r].z;
            o.w = SQRT2 * x.w + acc[r].w;
        }
        *(float4*)d = o;
    }
}

__global__ __launch_bounds__(512) void stageA_kernel(
    const float* __restrict__ y0, const float* __restrict__ y1,
    const float* __restrict__ y2, const float* __restrict__ y3)
{
    extern __shared__ float sm[];
    float* A = sm;
    float* B = sm + 128 * PA;
    float* C = sm + 2 * 128 * PA;

    const int img = blockIdx.x;
    const int b = img >> 6, ch = img & 63;
    const float* gY0;
    const float* gY1;
    if (ch < 32) { gY0 = y1 + (b * 32 + ch) * 16384;
                   gY1 = y0 + (b * 32 + ch) * 16384; }
    else         { gY0 = y2 + (b * 32 + ch - 32) * 16384;
                   gY1 = y3 + (b * 32 + ch - 32) * 16384; }

    const int tid  = threadIdx.x;
    const int lane = tid & 31;
    const int wrp  = tid >> 5;

    for (int idx = tid; idx < 4096; idx += 512) {
        const int i = idx >> 5, g = idx & 31;
        *(float4*)(A + i * PA + 4 * g) = *(const float4*)(gY0 + i * 128 + 4 * g);
    }
    __syncthreads();

    rowconvA<5>(A, B, wrp, lane);
    __syncthreads();
    colconvA<5, 0>(B, C, gY1, tid);
    __syncthreads();

    rowconvA<6>(C, B, wrp, lane);
    __syncthreads();
    colconvA<6, 1>(B, A, nullptr, tid);
    __syncthreads();

    float* gx = g_x + img * 32768;
    for (int idx = tid; idx < 32768; idx += 512) {
        const int i = idx >> 8, j = idx & 255;
        const int col = (i + j) & 255;
        const int hh = col >> 1;
        float v;
        if (col & 1) v = C[((i - 1 - hh) & 127) * PA + hh];
        else         v = A[((i - hh) & 127) * PA + hh];
        gx[idx] = v;
    }
}

// ---------------- Fused Stage B + qprec (4-CTA cluster, 2 CTA/SM) ----------

#define QP  264                     // q pitch: bank-free phase-3 reads
#define EP  268                     // 16B-aligned rows
#define Q0OFF 0                     // Q0: 32 x 264
#define Q1OFF 8464                  // 32*264 + 16 -> Q1 banks complement Q0's
#define EOFF  16912                 // E: 43 x 268
#define SMB_FLOATS (16912 + 43 * 268)
#define SMB_BYTES (SMB_FLOATS * 4)  // 113,744 B -> 2 CTAs/SM

__device__ __forceinline__ uint32_t smem_u32(const void* p) {
    uint32_t a;
    asm("{ .reg .u64 t; cvta.to.shared.u64 t, %1; cvt.u32.u64 %0, t; }"
        : "=r"(a) : "l"(p));
    return a;
}
__device__ __forceinline__ uint32_t mapa_rank(uint32_t addr, uint32_t rank) {
    uint32_t r;
    asm("mapa.shared::cluster.u32 %0, %1, %2;" : "=r"(r) : "r"(addr), "r"(rank));
    return r;
}
__device__ __forceinline__ float ld_dsm(uint32_t addr) {
    float v;
    asm volatile("ld.shared::cluster.f32 %0, [%1];" : "=f"(v) : "r"(addr));
    return v;
}
#define CLUSTER_SYNC() do { \
    asm volatile("barrier.cluster.arrive.aligned;" ::: "memory"); \
    asm volatile("barrier.cluster.wait.aligned;"  ::: "memory"); } while (0)

// In-place row conv, chunk-consumed window (register-light, ~96 FMA):
// out[c] = sum_u FILT[u]*Ein[c+u], lane owns cols [8L, 8L+8).
__device__ __forceinline__ void rowconv_inplace(float* __restrict__ erow,
                                                int lane)
{
    DEF_FILT;
    const float* tr = erow + 8 * lane;
    float acc[8];
    #pragma unroll
    for (int m = 0; m < 8; ++m) acc[m] = 0.f;
    #pragma unroll
    for (int v = 0; v < 5; ++v) {
        const float4 t = *(const float4*)(tr + 4 * v);
        const float tv[4] = {t.x, t.y, t.z, t.w};
        #pragma unroll
        for (int x = 0; x < 4; ++x) {
            const int e = 4 * v + x;
            #pragma unroll
            for (int m = 0; m < 8; ++m)
                if (e - m >= 0 && e - m < 12)
                    acc[m] = fmaf(FILT[e - m], tv[x], acc[m]);
        }
    }
    __syncwarp();
    float4 o0, o1;
    o0.x=acc[0]; o0.y=acc[1]; o0.z=acc[2]; o0.w=acc[3];
    o1.x=acc[4]; o1.y=acc[5]; o1.z=acc[6]; o1.w=acc[7];
    *(float4*)(erow + 8 * lane)     = o0;
    *(float4*)(erow + 8 * lane + 4) = o1;
}

__global__ __launch_bounds__(1024, 2) __cluster_dims__(4, 1, 1)
void stageB_fused(float* __restrict__ out)
{
    extern __shared__ float smB[];
    float* Q0 = smB + Q0OFF;
    float* Q1 = smB + Q1OFF;
    float* E  = smB + EOFF;

    const int tid  = threadIdx.x;
    const int lane = tid & 31;
    const int wrp  = tid >> 5;                // 0..31
    uint32_t qr;
    asm("mov.u32 %0, %%cluster_ctarank;" : "=r"(qr));
    const int q    = (int)qr;                 // 0..3: owns q-rows [32q,32q+32)
    const int img2 = blockIdx.x >> 2;
    const int x0base = ((img2 >> 5) * 64 + (img2 & 31)) * 32768;
    const float* x0g = g_x + x0base;
    const float* x1g = x0g + 32 * 32768;

    const uint32_t q1Local = smem_u32(Q1);

    DEF_FILT;

    // ==== phase 1: Q1 = -1/sqrt2 (x1 + sefilter(x0, off=5)) ===============
    {
        const int rowbase = 32 * q - 5;
        for (int k = wrp; k < 43; k += 32) {
            int gr = rowbase + k;
            int flip = 0;
            if (gr < 0)         { gr += 128; flip = 128; }
            else if (gr >= 128) { gr -= 128; flip = 128; }
            const float* srow = x0g + gr * 256;
            float* erow = E + k * EP;
            for (int c = lane; c < 267; c += 32)
                erow[c] = srow[((c - 5) & 255) ^ flip];
            __syncwarp();
            rowconv_inplace(erow, lane);
        }
        __syncthreads();

        // vertical conv + combine -> Q1: 2 rows x 4 cols per thread
        {
            const int cg = tid & 63;
            const int rs = (tid >> 6) * 2;    // local rows [rs, rs+2)
            float4 acc0 = {0,0,0,0}, acc1 = {0,0,0,0};
            #pragma unroll
            for (int k = 0; k < 13; ++k) {
                const float4 v = *(const float4*)(E + (rs + k) * EP + 4 * cg);
                if (k <= 11) acc0 = f4fma(FILT[k],     v, acc0);
                if (k >= 1)  acc1 = f4fma(FILT[k - 1], v, acc1);
            }
            const int gi = 32 * q + rs;
            const float4 xa = *(const float4*)(x1g + gi * 256 + 4 * cg);
            const float4 xb = *(const float4*)(x1g + (gi + 1) * 256 + 4 * cg);
            float4 o0, o1;
            o0.x = -INV_SQRT2 * (xa.x + acc0.x);
            o0.y = -INV_SQRT2 * (xa.y + acc0.y);
            o0.z = -INV_SQRT2 * (xa.z + acc0.z);
            o0.w = -INV_SQRT2 * (xa.w + acc0.w);
            o1.x = -INV_SQRT2 * (xb.x + acc1.x);
            o1.y = -INV_SQRT2 * (xb.y + acc1.y);
            o1.z = -INV_SQRT2 * (xb.z + acc1.z);
            o1.w = -INV_SQRT2 * (xb.w + acc1.w);
            *(float4*)(Q1 + rs * QP + 4 * cg)       = o0;
            *(float4*)(Q1 + (rs + 1) * QP + 4 * cg) = o1;
        }
    }

    CLUSTER_SYNC();     // all CTAs' Q1 complete before halo reads

    // ==== phase 2: Q0 = sqrt2*x0 + sefilter(Q1, off=6) ====================
    {
        const int rowbase = 32 * q - 6;
        for (int k = wrp; k < 43; k += 32) {
            int gr = rowbase + k;
            int flip = 0;
            if (gr < 0)         { gr += 128; flip = 128; }
            else if (gr >= 128) { gr -= 128; flip = 128; }
            const int owner = gr >> 5;        // warp-uniform, 0..3
            const int lr    = gr & 31;
            float* erow = E + k * EP;
            if (owner == q) {
                const float* qrow = Q1 + lr * QP;
                for (int c = lane; c < 267; c += 32)
                    erow[c] = qrow[((c - 6) & 255) ^ flip];
            } else {
                const uint32_t pb = mapa_rank(q1Local, (uint32_t)owner)
                                  + (uint32_t)(lr * QP) * 4u;
                for (int c = lane; c < 267; c += 32)
                    erow[c] = ld_dsm(pb + (uint32_t)(((c - 6) & 255) ^ flip) * 4u);
            }
            __syncwarp();
            rowconv_inplace(erow, lane);
        }
        __syncthreads();

        {
            const int cg = tid & 63;
            const int rs = (tid >> 6) * 2;
            float4 acc0 = {0,0,0,0}, acc1 = {0,0,0,0};
            #pragma unroll
            for (int k = 0; k < 13; ++k) {
                const float4 v = *(const float4*)(E + (rs + k) * EP + 4 * cg);
                if (k <= 11) acc0 = f4fma(FILT[k],     v, acc0);
                if (k >= 1)  acc1 = f4fma(FILT[k - 1], v, acc1);
            }
            const int gi = 32 * q + rs;
            const float4 xa = *(const float4*)(x0g + gi * 256 + 4 * cg);
            const float4 xb = *(const float4*)(x0g + (gi + 1) * 256 + 4 * cg);
            float4 o0, o1;
            o0.x = SQRT2 * xa.x + acc0.x;
            o0.y = SQRT2 * xa.y + acc0.y;
            o0.z = SQRT2 * xa.z + acc0.z;
            o0.w = SQRT2 * xa.w + acc0.w;
            o1.x = SQRT2 * xb.x + acc1.x;
            o1.y = SQRT2 * xb.y + acc1.y;
            o1.z = SQRT2 * xb.z + acc1.z;
            o1.w = SQRT2 * xb.w + acc1.w;
            *(float4*)(Q0 + rs * QP + 4 * cg)       = o0;
            *(float4*)(Q0 + (rs + 1) * QP + 4 * cg) = o1;
        }
        __syncthreads();
    }

    // ==== phase 3: qprec '1r' scatter — local rows only, bank-free ========
    // out[u,j]: row=(u+j)&255 in [64q,64q+64) <=> r=row>>1 in [32q,32q+32).
    {
        float* og = out + img2 * 65536;
        const int base64 = 64 * q;
        #pragma unroll
        for (int p = 0; p < 2; ++p) {
            const int row = base64 + 32 * p + lane;
            const int r   = row >> 1;
            const int lr  = (32 * p + lane) >> 1;
            const float* src = (lane & 1) ? (Q1 + lr * QP) : (Q0 + lr * QP);
            const int coff = (lane & 1) ? (-1 - r) : (-r);
            #pragma unroll
            for (int ui = 0; ui < 8; ++ui) {
                const int u = (wrp << 3) + ui;
                const int j = (base64 - u + 32 * p + lane) & 255;
                og[u * 256 + j] = src[(j + coff) & 255];
            }
        }
    }

    CLUSTER_SYNC();     // smem must outlive peers' phase-2 reads
}

// ---------------------------------------------------------------------------

extern "C" void kernel_launch(void* const* d_in, const int* in_sizes, int n_in,
                              void* d_out, int out_size)
{
    const float* y0 = (const float*)d_in[0];
    const float* y1 = (const float*)d_in[1];
    const float* y2 = (const float*)d_in[2];
    const float* y3 = (const float*)d_in[3];

    static bool once = []() {
        cudaFuncSetAttribute(stageA_kernel,
                             cudaFuncAttributeMaxDynamicSharedMemorySize,
                             3 * 128 * PA * 4);
        cudaFuncSetAttribute(stageB_fused,
                             cudaFuncAttributeMaxDynamicSharedMemorySize,
                             SMB_BYTES);
        return true;
    }();
    (void)once;

    stageA_kernel<<<512, 512, 3 * 128 * PA * 4>>>(y0, y1, y2, y3);
    stageB_fused<<<1024, 1024, SMB_BYTES>>>((float*)d_out);
}